// round 5
// baseline (speedup 1.0000x reference)
#include <cuda_runtime.h>
#include <cuda_bf16.h>
#include <cstdint>
#include <math.h>

#define DIM      512
#define MAXLEN   2048
#define SHD      128
#define EXPAND   1024
#define PROJ     2176
#define BATCH    8
#define MTOT     (BATCH*MAXLEN)   // 16384
#define HALF_R   1024

// ------------------- scratch (static device allocations) -------------------
__device__ __nv_bfloat16 g_xn [(size_t)MTOT*DIM];
__device__ __nv_bfloat16 g_W1b[(size_t)DIM*PROJ];
__device__ __nv_bfloat16 g_W2b[(size_t)EXPAND*DIM];
__device__ __nv_bfloat16 g_u  [(size_t)MTOT*EXPAND];
__device__ __nv_bfloat16 g_v  [(size_t)MTOT*EXPAND];
__device__ __nv_bfloat16 g_q  [(size_t)MTOT*SHD];
__device__ __nv_bfloat16 g_k  [(size_t)MTOT*SHD];
__device__ __nv_bfloat16 g_km [(size_t)BATCH*MAXLEN*MAXLEN];
__device__ __nv_bfloat16 g_o  [(size_t)MTOT*EXPAND];
__device__ float         g_f  [2*MAXLEN-1];

// --------------------------- PTX helpers ------------------------------------
__device__ __forceinline__ uint32_t smem_u32(const void* p) {
    uint32_t a;
    asm("{ .reg .u64 t; cvta.to.shared.u64 t, %1; cvt.u32.u64 %0, t; }" : "=r"(a) : "l"(p));
    return a;
}
__device__ __forceinline__ void ldsm4(uint32_t* r, uint32_t a) {
    asm volatile("ldmatrix.sync.aligned.m8n8.x4.shared.b16 {%0,%1,%2,%3}, [%4];"
        : "=r"(r[0]), "=r"(r[1]), "=r"(r[2]), "=r"(r[3]) : "r"(a));
}
__device__ __forceinline__ void ldsm4t(uint32_t* r, uint32_t a) {
    asm volatile("ldmatrix.sync.aligned.m8n8.x4.trans.shared.b16 {%0,%1,%2,%3}, [%4];"
        : "=r"(r[0]), "=r"(r[1]), "=r"(r[2]), "=r"(r[3]) : "r"(a));
}
__device__ __forceinline__ void mma16816(float* c, const uint32_t* a, uint32_t b0, uint32_t b1) {
    asm volatile("mma.sync.aligned.m16n8k16.row.col.f32.bf16.bf16.f32 "
        "{%0,%1,%2,%3}, {%4,%5,%6,%7}, {%8,%9}, {%0,%1,%2,%3};"
        : "+f"(c[0]), "+f"(c[1]), "+f"(c[2]), "+f"(c[3])
        : "r"(a[0]), "r"(a[1]), "r"(a[2]), "r"(a[3]), "r"(b0), "r"(b1));
}
#define CP16(dst, src) \
    asm volatile("cp.async.cg.shared.global [%0], [%1], 16;" :: "r"(dst), "l"(src))
#define CP_COMMIT() asm volatile("cp.async.commit_group;" ::: "memory")
#define CP_WAIT1()  asm volatile("cp.async.wait_group 1;" ::: "memory")

// ----------------------- pipelined mma.sync mainloop ------------------------
// BM=256, BN=128, BK=32, 3 stages, 512 threads = 16 warps (8M x 2N),
// warp tile 32x64 = 2 mtiles x 8 ntiles of m16n8k16.
// smem stage: A 256x(32+8) bf16 = 20480B ; B <= 10240B ; stride 30720B.
#define SSTAGE   30720
#define SMEM_DYN (3*SSTAGE)

template<int KTILES, bool BNT>
__device__ __forceinline__ void mainloop(const __nv_bfloat16* A, int lda,
                                         const __nv_bfloat16* B, int ldb,
                                         uint32_t s0, float (&C)[2][8][4]) {
    const int tid  = threadIdx.x;
    const int lane = tid & 31;
    const int warp = tid >> 5;
    const int wm = warp >> 1, wn = warp & 1;

    auto loadA = [&](int kt, int st) {
        const __nv_bfloat16* Ag = A + kt*32;
        uint32_t sa = s0 + st*SSTAGE;
        #pragma unroll
        for (int it = 0; it < 2; it++) {
            int r = (tid >> 2) + it*128, c = (tid & 3)*8;
            CP16(sa + (uint32_t)(r*40 + c)*2, Ag + (size_t)r*lda + c);
        }
    };
    auto loadB = [&](int kt, int st) {
        uint32_t sb = s0 + st*SSTAGE + 20480;
        if constexpr (BNT) {           // B is [N,K] row-major (K-major operand), 128xBK
            const __nv_bfloat16* Bg = B + kt*32;
            int r = tid >> 2, c = (tid & 3)*8;
            CP16(sb + (uint32_t)(r*40 + c)*2, Bg + (size_t)r*ldb + c);
        } else {                       // B is [K,N] row-major, BKx128
            const __nv_bfloat16* Bg = B + (size_t)kt*32*ldb;
            int r = tid >> 4, c = (tid & 15)*8;
            CP16(sb + (uint32_t)(r*136 + c)*2, Bg + (size_t)r*ldb + c);
        }
    };

    #pragma unroll
    for (int j = 0; j < 2; j++) {
        if (j < KTILES) { loadA(j, j); loadB(j, j); }
        CP_COMMIT();
    }

    for (int kt = 0; kt < KTILES; kt++) {
        int st = kt % 3;
        CP_WAIT1();
        __syncthreads();
        uint32_t sa = s0 + st*SSTAGE, sb = sa + 20480;
        #pragma unroll
        for (int kk = 0; kk < 2; kk++) {
            uint32_t a[2][4];
            #pragma unroll
            for (int mt = 0; mt < 2; mt++) {
                int row = wm*32 + mt*16 + (lane & 15);
                ldsm4(a[mt], sa + (uint32_t)(row*40 + kk*16 + (lane >> 4)*8)*2);
            }
            uint32_t b[4][4];
            #pragma unroll
            for (int nt2 = 0; nt2 < 4; nt2++) {
                if constexpr (BNT) {
                    int nrow = wn*64 + nt2*16 + ((lane >> 4) << 3) + (lane & 7);
                    int kcol = kk*16 + ((lane >> 3) & 1)*8;
                    ldsm4(b[nt2], sb + (uint32_t)(nrow*40 + kcol)*2);
                } else {
                    int krow = kk*16 + (lane & 15);
                    int ncol = wn*64 + nt2*16 + (lane >> 4)*8;
                    ldsm4t(b[nt2], sb + (uint32_t)(krow*136 + ncol)*2);
                }
            }
            #pragma unroll
            for (int mt = 0; mt < 2; mt++)
                #pragma unroll
                for (int nt = 0; nt < 8; nt++)
                    mma16816(C[mt][nt], a[mt], b[nt >> 1][(nt & 1)*2], b[nt >> 1][(nt & 1)*2 + 1]);
        }
        int jn = kt + 2;
        if (jn < KTILES) { loadA(jn, jn % 3); loadB(jn, jn % 3); }
        CP_COMMIT();
    }
}

#define ACC_INIT(C)                                                            \
    float C[2][8][4];                                                          \
    _Pragma("unroll") for (int i = 0; i < 2; i++)                              \
    _Pragma("unroll") for (int j = 0; j < 8; j++)                              \
    _Pragma("unroll") for (int l = 0; l < 4; l++) C[i][j][l] = 0.f;

#define EPI_COORDS                                                             \
    int lane = threadIdx.x & 31, warp = threadIdx.x >> 5;                      \
    int rbase = (blockIdx.y*256) + (warp >> 1)*32 + (lane >> 2);               \
    int cbase = (blockIdx.x*128) + (warp & 1)*64 + (lane & 3)*2;

// ------------------------------ small kernels ------------------------------
__global__ void cvtW1_kernel(const float* __restrict__ W1) {
    int i = blockIdx.x*blockDim.x + threadIdx.x;
    if (i < DIM*PROJ) g_W1b[i] = __float2bfloat16(W1[i]);
}
__global__ void cvtW2_kernel(const float* __restrict__ W2) {
    int i = blockIdx.x*blockDim.x + threadIdx.x;
    if (i < EXPAND*DIM) g_W2b[i] = __float2bfloat16(W2[i]);
}

__global__ void rmsnorm_kernel(const float* __restrict__ x,
                               const float* __restrict__ norm_scale) {
    int row = blockIdx.x;
    const float4* xr = (const float4*)(x + (size_t)row*DIM);
    float4 v = xr[threadIdx.x];
    float ss = v.x*v.x + v.y*v.y + v.z*v.z + v.w*v.w;
    __shared__ float red[128];
    red[threadIdx.x] = ss;
    __syncthreads();
    #pragma unroll
    for (int o = 64; o > 0; o >>= 1) {
        if (threadIdx.x < o) red[threadIdx.x] += red[threadIdx.x+o];
        __syncthreads();
    }
    float scale = rsqrtf(red[0]*(1.f/DIM) + 1e-6f) * norm_scale[0];
    __nv_bfloat162 p0 = __floats2bfloat162_rn(v.x*scale, v.y*scale);
    __nv_bfloat162 p1 = __floats2bfloat162_rn(v.z*scale, v.w*scale);
    size_t base = (size_t)row*DIM + threadIdx.x*4;
    *(__nv_bfloat162*)&g_xn[base]   = p0;
    *(__nv_bfloat162*)&g_xn[base+2] = p1;
}

// Toeplitz closed form with ±d pairing: f(d)=Σ P cos(θd)+Q sin(θd);
// f(-d) shares cos and negates the sin term.
__global__ void toeplitz_kernel(const float* __restrict__ ra,
                                const float* __restrict__ rb) {
    int dd = blockIdx.x;                  // 0..2047
    float d = (float)dd;
    float accp = 0.f, accn = 0.f;
    for (int j = threadIdx.x; j < HALF_R; j += 256) {
        float a1 = ra[j], a2 = ra[j+HALF_R];
        float b1 = rb[j], b2 = rb[j+HALF_R];
        float P = a1*b1 + a2*b2;
        float Q = a2*b1 - a1*b2;
        float inv = exp2f(-13.287712379549449f * (float)j * (1.f/HALF_R));
        float s, c;
        sincosf(inv*d, &s, &c);
        accp += P*c + Q*s;
        accn += P*c - Q*s;
    }
    __shared__ float redp[256], redn[256];
    redp[threadIdx.x] = accp;
    redn[threadIdx.x] = accn;
    __syncthreads();
    #pragma unroll
    for (int o = 128; o > 0; o >>= 1) {
        if (threadIdx.x < o) {
            redp[threadIdx.x] += redp[threadIdx.x+o];
            redn[threadIdx.x] += redn[threadIdx.x+o];
        }
        __syncthreads();
    }
    if (threadIdx.x == 0) {
        g_f[(MAXLEN-1) + dd] = redp[0];
        g_f[(MAXLEN-1) - dd] = redn[0];
    }
}

// ------------------------------- GEMM1 --------------------------------------
__global__ void __launch_bounds__(512,1) mma_gemm1(const float* __restrict__ b1,
                                                   const float* __restrict__ gamma,
                                                   const float* __restrict__ beta) {
    extern __shared__ __align__(16) char smem[];
    uint32_t s0 = smem_u32(smem);
    int row0 = blockIdx.y*256, col0 = blockIdx.x*128;
    ACC_INIT(C)
    mainloop<DIM/32, false>(g_xn + (size_t)row0*DIM, DIM, g_W1b + col0, PROJ, s0, C);
    EPI_COORDS
    #pragma unroll
    for (int mt = 0; mt < 2; mt++)
        #pragma unroll
        for (int nt = 0; nt < 8; nt++) {
            int n = cbase + nt*8;
            float bb0 = __ldg(&b1[n]), bb1 = __ldg(&b1[n+1]);
            #pragma unroll
            for (int h = 0; h < 2; h++) {
                int m = rbase + mt*16 + h*8;
                float v0 = C[mt][nt][h*2]   + bb0;
                float v1 = C[mt][nt][h*2+1] + bb1;
                v0 = v0 / (1.f + __expf(-v0));
                v1 = v1 / (1.f + __expf(-v1));
                if (n < EXPAND) {
                    *(__nv_bfloat162*)&g_u[(size_t)m*EXPAND + n] = __floats2bfloat162_rn(v0, v1);
                } else if (n < 2*EXPAND) {
                    *(__nv_bfloat162*)&g_v[(size_t)m*EXPAND + (n-EXPAND)] = __floats2bfloat162_rn(v0, v1);
                } else {
                    int s = n - 2*EXPAND;
                    float q0 = v0*__ldg(&gamma[s])       + __ldg(&beta[s]);
                    float q1 = v1*__ldg(&gamma[s+1])     + __ldg(&beta[s+1]);
                    float k0 = v0*__ldg(&gamma[SHD+s])   + __ldg(&beta[SHD+s]);
                    float k1 = v1*__ldg(&gamma[SHD+s+1]) + __ldg(&beta[SHD+s+1]);
                    *(__nv_bfloat162*)&g_q[(size_t)m*SHD + s] = __floats2bfloat162_rn(q0, q1);
                    *(__nv_bfloat162*)&g_k[(size_t)m*SHD + s] = __floats2bfloat162_rn(k0, k1);
                }
            }
        }
}

// ------------------------------- qk -----------------------------------------
// KM[b,m,n] = relu(q·k/2048 + f(n-m))^2   (NT, K=128)
__global__ void __launch_bounds__(512,1) mma_qk() {
    extern __shared__ __align__(16) char smem[];
    uint32_t s0 = smem_u32(smem);
    int b = blockIdx.z;
    int row0 = blockIdx.y*256, col0 = blockIdx.x*128;
    ACC_INIT(C)
    mainloop<SHD/32, true>(g_q + (size_t)b*MAXLEN*SHD + (size_t)row0*SHD, SHD,
                           g_k + (size_t)b*MAXLEN*SHD + (size_t)col0*SHD, SHD, s0, C);
    EPI_COORDS
    __nv_bfloat16* KM = g_km + (size_t)b*MAXLEN*MAXLEN;
    #pragma unroll
    for (int mt = 0; mt < 2; mt++)
        #pragma unroll
        for (int h = 0; h < 2; h++) {
            int m = rbase + mt*16 + h*8;
            const float* fp = g_f + (cbase - m + (MAXLEN-1));
            #pragma unroll
            for (int nt = 0; nt < 8; nt++) {
                float s0v = fmaxf(C[mt][nt][h*2]  *(1.f/MAXLEN) + fp[nt*8],   0.f);
                float s1v = fmaxf(C[mt][nt][h*2+1]*(1.f/MAXLEN) + fp[nt*8+1], 0.f);
                *(__nv_bfloat162*)&KM[(size_t)m*MAXLEN + cbase + nt*8] =
                    __floats2bfloat162_rn(s0v*s0v, s1v*s1v);
            }
        }
}

// ------------------------------- GEMM D -------------------------------------
// o = u * (KM @ v)   (NN, K=2048)
__global__ void __launch_bounds__(512,1) mma_gemmD() {
    extern __shared__ __align__(16) char smem[];
    uint32_t s0 = smem_u32(smem);
    int b = blockIdx.z;
    int row0 = blockIdx.y*256, col0 = blockIdx.x*128;
    ACC_INIT(C)
    mainloop<MAXLEN/32, false>(g_km + (size_t)b*MAXLEN*MAXLEN + (size_t)row0*MAXLEN, MAXLEN,
                               g_v  + (size_t)b*MAXLEN*EXPAND + col0, EXPAND, s0, C);
    EPI_COORDS
    #pragma unroll
    for (int mt = 0; mt < 2; mt++)
        #pragma unroll
        for (int h = 0; h < 2; h++) {
            int m = b*MAXLEN + rbase + mt*16 + h*8;
            #pragma unroll
            for (int nt = 0; nt < 8; nt++) {
                size_t gofs = (size_t)m*EXPAND + cbase + nt*8;
                __nv_bfloat162 u2 = *(const __nv_bfloat162*)&g_u[gofs];
                float o0 = C[mt][nt][h*2]   * __bfloat162float(u2.x);
                float o1 = C[mt][nt][h*2+1] * __bfloat162float(u2.y);
                *(__nv_bfloat162*)&g_o[gofs] = __floats2bfloat162_rn(o0, o1);
            }
        }
}

// ------------------------------- GEMM E -------------------------------------
// out = o @ W2 + b2 + x   (NN, K=1024)
__global__ void __launch_bounds__(512,1) mma_gemmE(const float* __restrict__ b2,
                                                   const float* __restrict__ x,
                                                   float* __restrict__ out) {
    extern __shared__ __align__(16) char smem[];
    uint32_t s0 = smem_u32(smem);
    int row0 = blockIdx.y*256, col0 = blockIdx.x*128;
    ACC_INIT(C)
    mainloop<EXPAND/32, false>(g_o + (size_t)row0*EXPAND, EXPAND, g_W2b + col0, DIM, s0, C);
    EPI_COORDS
    #pragma unroll
    for (int mt = 0; mt < 2; mt++)
        #pragma unroll
        for (int nt = 0; nt < 8; nt++) {
            int n = cbase + nt*8;
            float bb0 = __ldg(&b2[n]), bb1 = __ldg(&b2[n+1]);
            #pragma unroll
            for (int h = 0; h < 2; h++) {
                int m = rbase + mt*16 + h*8;
                size_t gofs = (size_t)m*DIM + n;
                float2 xv = *(const float2*)&x[gofs];
                float2 o;
                o.x = C[mt][nt][h*2]   + bb0 + xv.x;
                o.y = C[mt][nt][h*2+1] + bb1 + xv.y;
                *(float2*)&out[gofs] = o;
            }
        }
}

// ------------------------------- launch -------------------------------------
extern "C" void kernel_launch(void* const* d_in, const int* in_sizes, int n_in,
                              void* d_out, int out_size) {
    (void)in_sizes; (void)n_in; (void)out_size;
    const float* x     = (const float*)d_in[0];
    const float* W1    = (const float*)d_in[1];
    const float* b1    = (const float*)d_in[2];
    const float* W2    = (const float*)d_in[3];
    const float* b2    = (const float*)d_in[4];
    const float* ra    = (const float*)d_in[5];
    const float* rb    = (const float*)d_in[6];
    const float* gamma = (const float*)d_in[7];
    const float* beta  = (const float*)d_in[8];
    const float* ns    = (const float*)d_in[9];
    float* out = (float*)d_out;

    static bool attr_done = false;
    if (!attr_done) {
        cudaFuncSetAttribute(mma_gemm1, cudaFuncAttributeMaxDynamicSharedMemorySize, SMEM_DYN);
        cudaFuncSetAttribute(mma_qk,    cudaFuncAttributeMaxDynamicSharedMemorySize, SMEM_DYN);
        cudaFuncSetAttribute(mma_gemmD, cudaFuncAttributeMaxDynamicSharedMemorySize, SMEM_DYN);
        cudaFuncSetAttribute(mma_gemmE, cudaFuncAttributeMaxDynamicSharedMemorySize, SMEM_DYN);
        attr_done = true;
    }

    cvtW1_kernel<<<(DIM*PROJ + 511)/512, 512>>>(W1);
    cvtW2_kernel<<<(EXPAND*DIM + 511)/512, 512>>>(W2);
    rmsnorm_kernel<<<MTOT, 128>>>(x, ns);
    toeplitz_kernel<<<MAXLEN, 256>>>(ra, rb);

    mma_gemm1<<<dim3(PROJ/128, MTOT/256),            512, SMEM_DYN>>>(b1, gamma, beta);
    mma_qk   <<<dim3(MAXLEN/128, MAXLEN/256, BATCH), 512, SMEM_DYN>>>();
    mma_gemmD<<<dim3(EXPAND/128, MAXLEN/256, BATCH), 512, SMEM_DYN>>>();
    mma_gemmE<<<dim3(DIM/128, MTOT/256),             512, SMEM_DYN>>>(b2, x, out);
}

// round 6
// speedup vs baseline: 1.1141x; 1.1141x over previous
#include <cuda_runtime.h>
#include <cuda_bf16.h>
#include <cuda_fp8.h>
#include <cstdint>
#include <math.h>

#define DIM      512
#define MAXLEN   2048
#define SHD      128
#define EXPAND   1024
#define PROJ     2176
#define BATCH    8
#define MTOT     (BATCH*MAXLEN)   // 16384
#define HALF_R   1024

#define KM_SCALE   512.f
#define V_SCALE    16.f
#define OUT_DESCALE (1.f/(512.f*16.f))

// ------------------- scratch (static device allocations) -------------------
__device__ __nv_bfloat16 g_xn [(size_t)MTOT*DIM];
__device__ __nv_bfloat16 g_W1b[(size_t)DIM*PROJ];
__device__ __nv_bfloat16 g_W2b[(size_t)EXPAND*DIM];
__device__ __nv_bfloat16 g_u  [(size_t)MTOT*EXPAND];
__device__ __nv_bfloat16 g_v  [(size_t)MTOT*EXPAND];
__device__ __nv_bfloat16 g_q  [(size_t)MTOT*SHD];
__device__ __nv_bfloat16 g_k  [(size_t)MTOT*SHD];
__device__ uint8_t       g_km8[(size_t)BATCH*MAXLEN*MAXLEN];   // e4m3, x512
__device__ uint8_t       g_vT8[(size_t)BATCH*EXPAND*MAXLEN];   // e4m3, x16, [b][e][m]
__device__ __nv_bfloat16 g_o  [(size_t)MTOT*EXPAND];
__device__ float         g_f  [2*MAXLEN-1];

// --------------------------- PTX helpers ------------------------------------
__device__ __forceinline__ uint32_t smem_u32(const void* p) {
    uint32_t a;
    asm("{ .reg .u64 t; cvta.to.shared.u64 t, %1; cvt.u32.u64 %0, t; }" : "=r"(a) : "l"(p));
    return a;
}
__device__ __forceinline__ void ldsm4(uint32_t* r, uint32_t a) {
    asm volatile("ldmatrix.sync.aligned.m8n8.x4.shared.b16 {%0,%1,%2,%3}, [%4];"
        : "=r"(r[0]), "=r"(r[1]), "=r"(r[2]), "=r"(r[3]) : "r"(a));
}
__device__ __forceinline__ void ldsm4t(uint32_t* r, uint32_t a) {
    asm volatile("ldmatrix.sync.aligned.m8n8.x4.trans.shared.b16 {%0,%1,%2,%3}, [%4];"
        : "=r"(r[0]), "=r"(r[1]), "=r"(r[2]), "=r"(r[3]) : "r"(a));
}
template<bool FP8>
__device__ __forceinline__ void mma_any(float* c, const uint32_t* a, uint32_t b0, uint32_t b1) {
    if constexpr (FP8) {
        asm volatile("mma.sync.aligned.m16n8k32.row.col.f32.e4m3.e4m3.f32 "
            "{%0,%1,%2,%3}, {%4,%5,%6,%7}, {%8,%9}, {%0,%1,%2,%3};"
            : "+f"(c[0]), "+f"(c[1]), "+f"(c[2]), "+f"(c[3])
            : "r"(a[0]), "r"(a[1]), "r"(a[2]), "r"(a[3]), "r"(b0), "r"(b1));
    } else {
        asm volatile("mma.sync.aligned.m16n8k16.row.col.f32.bf16.bf16.f32 "
            "{%0,%1,%2,%3}, {%4,%5,%6,%7}, {%8,%9}, {%0,%1,%2,%3};"
            : "+f"(c[0]), "+f"(c[1]), "+f"(c[2]), "+f"(c[3])
            : "r"(a[0]), "r"(a[1]), "r"(a[2]), "r"(a[3]), "r"(b0), "r"(b1));
    }
}
#define CP16(dst, src) \
    asm volatile("cp.async.cg.shared.global [%0], [%1], 16;" :: "r"(dst), "l"(src))
#define CP_COMMIT() asm volatile("cp.async.commit_group;" ::: "memory")
#define CP_WAIT2()  asm volatile("cp.async.wait_group 2;" ::: "memory")

// ----------------------- pipelined mma.sync mainloop ------------------------
// BM=128, BN=128, BK=32 b16-units, 4 stages, 256 threads = 8 warps (4M x 2N),
// warp tile 32x64 = 2 mtiles x 8 ntiles of m16n8 (k16 bf16 / k32 fp8).
// Element unit throughout is a 16-bit lane (bf16, or an fp8 pair).
// smem stage: A 128x(32+8) u = 10240B ; B <= 10240B ; stride 20480B.
#define SSTAGE   20480
#define SMEM_DYN (4*SSTAGE)

template<int KTILES, bool BNT, bool FP8>
__device__ __forceinline__ void mainloop(const __nv_bfloat16* A, int lda,
                                         const __nv_bfloat16* B, int ldb,
                                         uint32_t s0, float (&C)[2][8][4]) {
    const int tid  = threadIdx.x;
    const int lane = tid & 31;
    const int warp = tid >> 5;
    const int wm = warp >> 1, wn = warp & 1;

    auto loadA = [&](int kt, int st) {
        const __nv_bfloat16* Ag = A + kt*32;
        uint32_t sa = s0 + st*SSTAGE;
        #pragma unroll
        for (int it = 0; it < 2; it++) {
            int r = (tid >> 2) + it*64, c = (tid & 3)*8;
            CP16(sa + (uint32_t)(r*40 + c)*2, Ag + (size_t)r*lda + c);
        }
    };
    auto loadB = [&](int kt, int st) {
        uint32_t sb = s0 + st*SSTAGE + 10240;
        if constexpr (BNT) {           // B is [N,K] row-major (K-major operand)
            const __nv_bfloat16* Bg = B + kt*32;
            #pragma unroll
            for (int it = 0; it < 2; it++) {
                int r = (tid >> 2) + it*64, c = (tid & 3)*8;
                CP16(sb + (uint32_t)(r*40 + c)*2, Bg + (size_t)r*ldb + c);
            }
        } else {                       // B is [K,N] row-major
            const __nv_bfloat16* Bg = B + (size_t)kt*32*ldb;
            #pragma unroll
            for (int it = 0; it < 2; it++) {
                int r = (tid >> 4) + it*16, c = (tid & 15)*8;
                CP16(sb + (uint32_t)(r*136 + c)*2, Bg + (size_t)r*ldb + c);
            }
        }
    };

    #pragma unroll
    for (int j = 0; j < 3; j++) {
        if (j < KTILES) { loadA(j, j); loadB(j, j); }
        CP_COMMIT();
    }

    for (int kt = 0; kt < KTILES; kt++) {
        int st = kt & 3;
        CP_WAIT2();
        __syncthreads();
        uint32_t sa = s0 + st*SSTAGE, sb = sa + 10240;
        #pragma unroll
        for (int kk = 0; kk < 2; kk++) {
            uint32_t a[2][4];
            #pragma unroll
            for (int mt = 0; mt < 2; mt++) {
                int row = wm*32 + mt*16 + (lane & 15);
                ldsm4(a[mt], sa + (uint32_t)(row*40 + kk*16 + (lane >> 4)*8)*2);
            }
            uint32_t b[4][4];
            #pragma unroll
            for (int nt2 = 0; nt2 < 4; nt2++) {
                if constexpr (BNT) {
                    int nrow = wn*64 + nt2*16 + ((lane >> 4) << 3) + (lane & 7);
                    int kcol = kk*16 + ((lane >> 3) & 1)*8;
                    ldsm4(b[nt2], sb + (uint32_t)(nrow*40 + kcol)*2);
                } else {
                    int krow = kk*16 + (lane & 15);
                    int ncol = wn*64 + nt2*16 + (lane >> 4)*8;
                    ldsm4t(b[nt2], sb + (uint32_t)(krow*136 + ncol)*2);
                }
            }
            #pragma unroll
            for (int mt = 0; mt < 2; mt++)
                #pragma unroll
                for (int nt = 0; nt < 8; nt++)
                    mma_any<FP8>(C[mt][nt], a[mt], b[nt >> 1][(nt & 1)*2], b[nt >> 1][(nt & 1)*2 + 1]);
        }
        int jn = kt + 3;
        if (jn < KTILES) { loadA(jn, jn & 3); loadB(jn, jn & 3); }
        CP_COMMIT();
    }
}

#define ACC_INIT(C)                                                            \
    float C[2][8][4];                                                          \
    _Pragma("unroll") for (int i = 0; i < 2; i++)                              \
    _Pragma("unroll") for (int j = 0; j < 8; j++)                              \
    _Pragma("unroll") for (int l = 0; l < 4; l++) C[i][j][l] = 0.f;

#define EPI_COORDS                                                             \
    int lane = threadIdx.x & 31, warp = threadIdx.x >> 5;                      \
    int rbase = (blockIdx.y*128) + (warp >> 1)*32 + (lane >> 2);               \
    int cbase = (blockIdx.x*128) + (warp & 1)*64 + (lane & 3)*2;

// ------------------------------ small kernels ------------------------------
__global__ void cvtW1_kernel(const float* __restrict__ W1) {
    int i = blockIdx.x*blockDim.x + threadIdx.x;
    if (i < DIM*PROJ) g_W1b[i] = __float2bfloat16(W1[i]);
}
__global__ void cvtW2_kernel(const float* __restrict__ W2) {
    int i = blockIdx.x*blockDim.x + threadIdx.x;
    if (i < EXPAND*DIM) g_W2b[i] = __float2bfloat16(W2[i]);
}

__global__ void rmsnorm_kernel(const float* __restrict__ x,
                               const float* __restrict__ norm_scale) {
    int row = blockIdx.x;
    const float4* xr = (const float4*)(x + (size_t)row*DIM);
    float4 v = xr[threadIdx.x];
    float ss = v.x*v.x + v.y*v.y + v.z*v.z + v.w*v.w;
    __shared__ float red[128];
    red[threadIdx.x] = ss;
    __syncthreads();
    #pragma unroll
    for (int o = 64; o > 0; o >>= 1) {
        if (threadIdx.x < o) red[threadIdx.x] += red[threadIdx.x+o];
        __syncthreads();
    }
    float scale = rsqrtf(red[0]*(1.f/DIM) + 1e-6f) * norm_scale[0];
    __nv_bfloat162 p0 = __floats2bfloat162_rn(v.x*scale, v.y*scale);
    __nv_bfloat162 p1 = __floats2bfloat162_rn(v.z*scale, v.w*scale);
    size_t base = (size_t)row*DIM + threadIdx.x*4;
    *(__nv_bfloat162*)&g_xn[base]   = p0;
    *(__nv_bfloat162*)&g_xn[base+2] = p1;
}

// Toeplitz closed form with +-d pairing
__global__ void toeplitz_kernel(const float* __restrict__ ra,
                                const float* __restrict__ rb) {
    int dd = blockIdx.x;                  // 0..2047
    float d = (float)dd;
    float accp = 0.f, accn = 0.f;
    for (int j = threadIdx.x; j < HALF_R; j += 256) {
        float a1 = ra[j], a2 = ra[j+HALF_R];
        float b1 = rb[j], b2 = rb[j+HALF_R];
        float P = a1*b1 + a2*b2;
        float Q = a2*b1 - a1*b2;
        float inv = exp2f(-13.287712379549449f * (float)j * (1.f/HALF_R));
        float s, c;
        sincosf(inv*d, &s, &c);
        accp += P*c + Q*s;
        accn += P*c - Q*s;
    }
    __shared__ float redp[256], redn[256];
    redp[threadIdx.x] = accp;
    redn[threadIdx.x] = accn;
    __syncthreads();
    #pragma unroll
    for (int o = 128; o > 0; o >>= 1) {
        if (threadIdx.x < o) {
            redp[threadIdx.x] += redp[threadIdx.x+o];
            redn[threadIdx.x] += redn[threadIdx.x+o];
        }
        __syncthreads();
    }
    if (threadIdx.x == 0) {
        g_f[(MAXLEN-1) + dd] = redp[0];
        g_f[(MAXLEN-1) - dd] = redn[0];
    }
}

// v [b,m,e] bf16 -> vT8 [b,e,m] e4m3 scaled x16
__global__ void vT8_kernel() {
    __shared__ float t[32][33];
    int b  = blockIdx.z;
    int e0 = blockIdx.x*32, m0 = blockIdx.y*32;
    int tx = threadIdx.x, ty = threadIdx.y;      // block (32,8)
    #pragma unroll
    for (int kk = 0; kk < 4; kk++) {
        int m = m0 + ty + kk*8;
        t[ty + kk*8][tx] = __bfloat162float(g_v[(size_t)(b*MAXLEN + m)*EXPAND + e0 + tx]);
    }
    __syncthreads();
    int idx = ty*32 + tx;                        // 0..255
    int e   = idx >> 3;                          // 0..31
    int mq  = (idx & 7)*4;                       // 0,4,..28
    float2 lo = make_float2(t[mq+0][e]*V_SCALE, t[mq+1][e]*V_SCALE);
    float2 hi = make_float2(t[mq+2][e]*V_SCALE, t[mq+3][e]*V_SCALE);
    uint32_t p = (uint32_t)__nv_cvt_float2_to_fp8x2(lo, __NV_SATFINITE, __NV_E4M3)
               | ((uint32_t)__nv_cvt_float2_to_fp8x2(hi, __NV_SATFINITE, __NV_E4M3) << 16);
    *(uint32_t*)&g_vT8[(size_t)(b*EXPAND + e0 + e)*MAXLEN + m0 + mq] = p;
}

// ------------------------------- GEMM1 --------------------------------------
__global__ void __launch_bounds__(256,2) mma_gemm1(const float* __restrict__ b1,
                                                   const float* __restrict__ gamma,
                                                   const float* __restrict__ beta) {
    extern __shared__ __align__(16) char smem[];
    uint32_t s0 = smem_u32(smem);
    int row0 = blockIdx.y*128, col0 = blockIdx.x*128;
    ACC_INIT(C)
    mainloop<DIM/32, false, false>(g_xn + (size_t)row0*DIM, DIM, g_W1b + col0, PROJ, s0, C);
    EPI_COORDS
    #pragma unroll
    for (int mt = 0; mt < 2; mt++)
        #pragma unroll
        for (int nt = 0; nt < 8; nt++) {
            int n = cbase + nt*8;
            float bb0 = __ldg(&b1[n]), bb1 = __ldg(&b1[n+1]);
            #pragma unroll
            for (int h = 0; h < 2; h++) {
                int m = rbase + mt*16 + h*8;
                float v0 = C[mt][nt][h*2]   + bb0;
                float v1 = C[mt][nt][h*2+1] + bb1;
                v0 = v0 / (1.f + __expf(-v0));
                v1 = v1 / (1.f + __expf(-v1));
                if (n < EXPAND) {
                    *(__nv_bfloat162*)&g_u[(size_t)m*EXPAND + n] = __floats2bfloat162_rn(v0, v1);
                } else if (n < 2*EXPAND) {
                    *(__nv_bfloat162*)&g_v[(size_t)m*EXPAND + (n-EXPAND)] = __floats2bfloat162_rn(v0, v1);
                } else {
                    int s = n - 2*EXPAND;
                    float q0 = v0*__ldg(&gamma[s])       + __ldg(&beta[s]);
                    float q1 = v1*__ldg(&gamma[s+1])     + __ldg(&beta[s+1]);
                    float k0 = v0*__ldg(&gamma[SHD+s])   + __ldg(&beta[SHD+s]);
                    float k1 = v1*__ldg(&gamma[SHD+s+1]) + __ldg(&beta[SHD+s+1]);
                    *(__nv_bfloat162*)&g_q[(size_t)m*SHD + s] = __floats2bfloat162_rn(q0, q1);
                    *(__nv_bfloat162*)&g_k[(size_t)m*SHD + s] = __floats2bfloat162_rn(k0, k1);
                }
            }
        }
}

// ------------------------------- qk -----------------------------------------
// km8[b,m,n] = e4m3( KM_SCALE * relu(q.k/2048 + f(n-m))^2 )   (NT, K=128)
__global__ void __launch_bounds__(256,2) mma_qk() {
    extern __shared__ __align__(16) char smem[];
    uint32_t s0 = smem_u32(smem);
    int b = blockIdx.z;
    int row0 = blockIdx.y*128, col0 = blockIdx.x*128;
    ACC_INIT(C)
    mainloop<SHD/32, true, false>(g_q + (size_t)b*MAXLEN*SHD + (size_t)row0*SHD, SHD,
                                  g_k + (size_t)b*MAXLEN*SHD + (size_t)col0*SHD, SHD, s0, C);
    EPI_COORDS
    uint8_t* KM = g_km8 + (size_t)b*MAXLEN*MAXLEN;
    #pragma unroll
    for (int mt = 0; mt < 2; mt++)
        #pragma unroll
        for (int h = 0; h < 2; h++) {
            int m = rbase + mt*16 + h*8;
            const float* fp = g_f + (cbase - m + (MAXLEN-1));
            #pragma unroll
            for (int nt = 0; nt < 8; nt++) {
                float s0v = fmaxf(C[mt][nt][h*2]  *(1.f/MAXLEN) + fp[nt*8],   0.f);
                float s1v = fmaxf(C[mt][nt][h*2+1]*(1.f/MAXLEN) + fp[nt*8+1], 0.f);
                float2 pr = make_float2(s0v*s0v*KM_SCALE, s1v*s1v*KM_SCALE);
                *(uint16_t*)&KM[(size_t)m*MAXLEN + cbase + nt*8] =
                    (uint16_t)__nv_cvt_float2_to_fp8x2(pr, __NV_SATFINITE, __NV_E4M3);
            }
        }
}

// ------------------------------- GEMM D (fp8) --------------------------------
// o = u * (km @ v) / (KM_SCALE*V_SCALE)
// A = km8[b] [2048 m, 2048 k] row-major fp8 ; B = vT8[b] [1024 n, 2048 k] fp8.
// Both K-major -> BNT mainloop on b16-pair view (lda/ldb = 1024 units).
__global__ void __launch_bounds__(256,2) mma_gemmD() {
    extern __shared__ __align__(16) char smem[];
    uint32_t s0 = smem_u32(smem);
    int b = blockIdx.z;
    int row0 = blockIdx.y*128, col0 = blockIdx.x*128;
    ACC_INIT(C)
    const __nv_bfloat16* A = (const __nv_bfloat16*)(g_km8 + (size_t)b*MAXLEN*MAXLEN + (size_t)row0*MAXLEN);
    const __nv_bfloat16* B = (const __nv_bfloat16*)(g_vT8 + (size_t)b*EXPAND*MAXLEN + (size_t)col0*MAXLEN);
    mainloop<MAXLEN/64, true, true>(A, MAXLEN/2, B, MAXLEN/2, s0, C);
    EPI_COORDS
    #pragma unroll
    for (int mt = 0; mt < 2; mt++)
        #pragma unroll
        for (int h = 0; h < 2; h++) {
            int m = b*MAXLEN + rbase + mt*16 + h*8;
            #pragma unroll
            for (int nt = 0; nt < 8; nt++) {
                size_t gofs = (size_t)m*EXPAND + cbase + nt*8;
                __nv_bfloat162 u2 = *(const __nv_bfloat162*)&g_u[gofs];
                float o0 = C[mt][nt][h*2]   * OUT_DESCALE * __bfloat162float(u2.x);
                float o1 = C[mt][nt][h*2+1] * OUT_DESCALE * __bfloat162float(u2.y);
                *(__nv_bfloat162*)&g_o[gofs] = __floats2bfloat162_rn(o0, o1);
            }
        }
}

// ------------------------------- GEMM E -------------------------------------
// out = o @ W2 + b2 + x   (NN, K=1024)
__global__ void __launch_bounds__(256,2) mma_gemmE(const float* __restrict__ b2,
                                                   const float* __restrict__ x,
                                                   float* __restrict__ out) {
    extern __shared__ __align__(16) char smem[];
    uint32_t s0 = smem_u32(smem);
    int row0 = blockIdx.y*128, col0 = blockIdx.x*128;
    ACC_INIT(C)
    mainloop<EXPAND/32, false, false>(g_o + (size_t)row0*EXPAND, EXPAND, g_W2b + col0, DIM, s0, C);
    EPI_COORDS
    #pragma unroll
    for (int mt = 0; mt < 2; mt++)
        #pragma unroll
        for (int nt = 0; nt < 8; nt++) {
            int n = cbase + nt*8;
            float bb0 = __ldg(&b2[n]), bb1 = __ldg(&b2[n+1]);
            #pragma unroll
            for (int h = 0; h < 2; h++) {
                int m = rbase + mt*16 + h*8;
                size_t gofs = (size_t)m*DIM + n;
                float2 xv = *(const float2*)&x[gofs];
                float2 o;
                o.x = C[mt][nt][h*2]   + bb0 + xv.x;
                o.y = C[mt][nt][h*2+1] + bb1 + xv.y;
                *(float2*)&out[gofs] = o;
            }
        }
}

// ------------------------------- launch -------------------------------------
extern "C" void kernel_launch(void* const* d_in, const int* in_sizes, int n_in,
                              void* d_out, int out_size) {
    (void)in_sizes; (void)n_in; (void)out_size;
    const float* x     = (const float*)d_in[0];
    const float* W1    = (const float*)d_in[1];
    const float* b1    = (const float*)d_in[2];
    const float* W2    = (const float*)d_in[3];
    const float* b2    = (const float*)d_in[4];
    const float* ra    = (const float*)d_in[5];
    const float* rb    = (const float*)d_in[6];
    const float* gamma = (const float*)d_in[7];
    const float* beta  = (const float*)d_in[8];
    const float* ns    = (const float*)d_in[9];
    float* out = (float*)d_out;

    cudaFuncSetAttribute(mma_gemm1, cudaFuncAttributeMaxDynamicSharedMemorySize, SMEM_DYN);
    cudaFuncSetAttribute(mma_qk,    cudaFuncAttributeMaxDynamicSharedMemorySize, SMEM_DYN);
    cudaFuncSetAttribute(mma_gemmD, cudaFuncAttributeMaxDynamicSharedMemorySize, SMEM_DYN);
    cudaFuncSetAttribute(mma_gemmE, cudaFuncAttributeMaxDynamicSharedMemorySize, SMEM_DYN);

    cvtW1_kernel<<<(DIM*PROJ + 511)/512, 512>>>(W1);
    cvtW2_kernel<<<(EXPAND*DIM + 511)/512, 512>>>(W2);
    rmsnorm_kernel<<<MTOT, 128>>>(x, ns);
    toeplitz_kernel<<<MAXLEN, 256>>>(ra, rb);

    mma_gemm1<<<dim3(PROJ/128, MTOT/128),            256, SMEM_DYN>>>(b1, gamma, beta);
    vT8_kernel<<<dim3(EXPAND/32, MAXLEN/32, BATCH),  dim3(32,8)>>>();
    mma_qk   <<<dim3(MAXLEN/128, MAXLEN/128, BATCH), 256, SMEM_DYN>>>();
    mma_gemmD<<<dim3(EXPAND/128, MAXLEN/128, BATCH), 256, SMEM_DYN>>>();
    mma_gemmE<<<dim3(DIM/128, MTOT/128),             256, SMEM_DYN>>>(b2, x, out);
}